// round 2
// baseline (speedup 1.0000x reference)
#include <cuda_runtime.h>

#define Bb 4
#define Cc 64
#define Nn 8192
#define Kk 16
#define Dd 64

// ---------------- scratch (static __device__, no allocations) ----------------
__device__ __align__(16) float g_xT[Bb * Nn * Cc];       // x transposed: (B, N, C)
__device__ float g_sq[Bb * Nn];                          // squared norms of pos
__device__ int   g_idx[Bb * Nn * Kk];                    // knn indices
__device__ __align__(16) float g_WsumNeg[Cc * Dd];       // -sum_k W[k,c,d]
__device__ float g_partial[(Bb * Nn / 64) * 2 * Dd];     // per-block BN partials (sum, sumsq)
__device__ float g_scale[Dd], g_shift[Dd];

// ---------------- prep: squared norms of pos --------------------------------
// Match XLA reduce lowering exactly: ((x*x + y*y) + z*z), no fma contraction.
__global__ void prep_sq(const float* __restrict__ pos) {
    int b = blockIdx.y;
    int n = blockIdx.x * 256 + threadIdx.x;
    const float* pb = pos + b * 3 * Nn;
    float x = pb[n], y = pb[Nn + n], z = pb[2 * Nn + n];
    float s = __fadd_rn(__fadd_rn(__fmul_rn(x, x), __fmul_rn(y, y)), __fmul_rn(z, z));
    g_sq[b * Nn + n] = s;
}

// ---------------- prep: transpose x (B,C,N) -> xT (B,N,C) -------------------
__global__ void prep_xT(const float* __restrict__ x) {
    __shared__ float t[32][33];
    int b = blockIdx.z;
    int n0 = blockIdx.x * 32, c0 = blockIdx.y * 32;
    int tx = threadIdx.x, ty = threadIdx.y;
#pragma unroll
    for (int i = 0; i < 4; ++i)
        t[ty + 8 * i][tx] = x[(size_t)b * Cc * Nn + (size_t)(c0 + ty + 8 * i) * Nn + n0 + tx];
    __syncthreads();
#pragma unroll
    for (int i = 0; i < 4; ++i)
        g_xT[(size_t)b * Nn * Cc + (size_t)(n0 + ty + 8 * i) * Cc + c0 + tx] = t[tx][ty + 8 * i];
}

// ---------------- prep: negated filter k-sum --------------------------------
__global__ void prep_wsum(const float* __restrict__ filt) {
    int i = blockIdx.x * 256 + threadIdx.x;  // 0..4095 = c*64+d
    float s = 0.f;
#pragma unroll
    for (int k = 0; k < Kk; ++k) s += filt[k * Cc * Dd + i];
    g_WsumNeg[i] = -s;
}

// ---------------- KNN: one thread per query, top-16 by neg squared dist -----
// inner matches cuBLAS K=3 fma chain: fma(z,z', fma(y,y', x*x'))
// dn matches XLA elementwise: (2*inner - sq_query) - sq_cand, left-assoc.
__global__ void knn_kernel(const float* __restrict__ pos) {
    __shared__ float sx[2048], sy[2048], sz[2048], ss[2048];
    int b = blockIdx.y;
    int n = blockIdx.x * 256 + threadIdx.x;
    const float* pb = pos + b * 3 * Nn;
    float qx = pb[n], qy = pb[Nn + n], qz = pb[2 * Nn + n];
    float qs = g_sq[b * Nn + n];

    float v[16];
    int id[16];
#pragma unroll
    for (int j = 0; j < 16; ++j) { v[j] = -3.4e38f; id[j] = 0x7FFFFFFF; }

    for (int c0 = 0; c0 < Nn; c0 += 2048) {
        __syncthreads();
        for (int j = threadIdx.x; j < 2048; j += 256) {
            sx[j] = pb[c0 + j];
            sy[j] = pb[Nn + c0 + j];
            sz[j] = pb[2 * Nn + c0 + j];
            ss[j] = g_sq[b * Nn + c0 + j];
        }
        __syncthreads();
#pragma unroll 4
        for (int j = 0; j < 2048; ++j) {
            float inner = __fmaf_rn(qz, sz[j], __fmaf_rn(qy, sy[j], __fmul_rn(qx, sx[j])));
            float dn = __fadd_rn(__fadd_rn(__fmul_rn(2.0f, inner), -qs), -ss[j]);
            if (dn > v[15]) {
                float cv = dn; int ci = c0 + j;
#pragma unroll
                for (int t = 0; t < 16; ++t) {
                    bool gt = (cv > v[t]) || (cv == v[t] && ci < id[t]);
                    float tv = v[t]; int ti = id[t];
                    if (gt) { v[t] = cv; id[t] = ci; cv = tv; ci = ti; }
                }
            }
        }
    }
#pragma unroll
    for (int j = 0; j < 16; ++j) g_idx[((size_t)b * Nn + n) * Kk + j] = id[j];
}

// ---------------- fused gather + spectral GEMM + BN partials ----------------
// out tile: 64 points x 64 D per block. 17 reduction stages:
//   k = 0..15: E = xT[neighbor_k], W = filter_k
//   k = 16   : E = xT[self],       W = -sum_k filter_k   (edge self term)
__global__ void gconv_kernel(const float* __restrict__ filt, float* __restrict__ out) {
    __shared__ __align__(16) float Esm[64 * 64];  // [c][p]
    __shared__ __align__(16) float Wsm[64 * 64];  // [c][d]
    int b = blockIdx.y;
    int n0 = blockIdx.x * 64;
    int tid = threadIdx.x;
    int tx = tid & 15, ty = tid >> 4;         // d-quad, p-quad
    int p = tid & 63, cg = tid >> 6;          // staging roles

    float acc[4][4];
#pragma unroll
    for (int i = 0; i < 4; ++i)
#pragma unroll
        for (int j = 0; j < 4; ++j) acc[i][j] = 0.f;

    const float* xTb = g_xT + (size_t)b * Nn * Cc;

    for (int kk = 0; kk <= Kk; ++kk) {
        // stage W (4096 floats)
        const float* Wsrc = (kk < Kk) ? (filt + kk * Cc * Dd) : g_WsumNeg;
#pragma unroll
        for (int i = 0; i < 4; ++i)
            ((float4*)Wsm)[tid + 256 * i] = ((const float4*)Wsrc)[tid + 256 * i];
        // stage E (gathered, transposed to [c][p])
        int m = (kk < Kk) ? g_idx[((size_t)b * Nn + n0 + p) * Kk + kk] : (n0 + p);
        const float* row = xTb + (size_t)m * Cc + cg * 16;
#pragma unroll
        for (int i = 0; i < 4; ++i) {
            float4 vv = ((const float4*)row)[i];
            int c = cg * 16 + i * 4;
            Esm[(c + 0) * 64 + p] = vv.x;
            Esm[(c + 1) * 64 + p] = vv.y;
            Esm[(c + 2) * 64 + p] = vv.z;
            Esm[(c + 3) * 64 + p] = vv.w;
        }
        __syncthreads();
#pragma unroll 8
        for (int c = 0; c < 64; ++c) {
            float4 e = *(const float4*)&Esm[c * 64 + ty * 4];
            float4 w = *(const float4*)&Wsm[c * 64 + tx * 4];
            acc[0][0] = fmaf(e.x, w.x, acc[0][0]);
            acc[0][1] = fmaf(e.x, w.y, acc[0][1]);
            acc[0][2] = fmaf(e.x, w.z, acc[0][2]);
            acc[0][3] = fmaf(e.x, w.w, acc[0][3]);
            acc[1][0] = fmaf(e.y, w.x, acc[1][0]);
            acc[1][1] = fmaf(e.y, w.y, acc[1][1]);
            acc[1][2] = fmaf(e.y, w.z, acc[1][2]);
            acc[1][3] = fmaf(e.y, w.w, acc[1][3]);
            acc[2][0] = fmaf(e.z, w.x, acc[2][0]);
            acc[2][1] = fmaf(e.z, w.y, acc[2][1]);
            acc[2][2] = fmaf(e.z, w.z, acc[2][2]);
            acc[2][3] = fmaf(e.z, w.w, acc[2][3]);
            acc[3][0] = fmaf(e.w, w.x, acc[3][0]);
            acc[3][1] = fmaf(e.w, w.y, acc[3][1]);
            acc[3][2] = fmaf(e.w, w.z, acc[3][2]);
            acc[3][3] = fmaf(e.w, w.w, acc[3][3]);
        }
        __syncthreads();
    }

    // BN partials from registers
    float psum[4], psq[4];
#pragma unroll
    for (int j = 0; j < 4; ++j) {
        psum[j] = acc[0][j] + acc[1][j] + acc[2][j] + acc[3][j];
        psq[j] = acc[0][j] * acc[0][j] + acc[1][j] * acc[1][j] +
                 acc[2][j] * acc[2][j] + acc[3][j] * acc[3][j];
    }
    // transpose tile to [d][p] via Esm; stash psum in Wsm
#pragma unroll
    for (int i = 0; i < 4; ++i)
#pragma unroll
        for (int j = 0; j < 4; ++j)
            Esm[(tx * 4 + j) * 64 + (ty * 4 + i)] = acc[i][j];
#pragma unroll
    for (int j = 0; j < 4; ++j) Wsm[ty * 64 + tx * 4 + j] = psum[j];
    __syncthreads();

    // write pre-BN result directly into d_out as (B, D, N)
    {
        int d = tid >> 2, seg = tid & 3;
        float4* orow = (float4*)(out + (size_t)b * Dd * Nn + (size_t)d * Nn + n0);
        const float4* trow = (const float4*)&Esm[d * 64];
#pragma unroll
        for (int q = 0; q < 4; ++q) orow[seg * 4 + q] = trow[seg * 4 + q];
    }
    int blk = b * gridDim.x + blockIdx.x;
    if (tid < 64) {
        float s = 0.f;
#pragma unroll
        for (int t = 0; t < 16; ++t) s += Wsm[t * 64 + tid];
        g_partial[blk * 128 + tid] = s;
    }
    __syncthreads();
#pragma unroll
    for (int j = 0; j < 4; ++j) Wsm[ty * 64 + tx * 4 + j] = psq[j];
    __syncthreads();
    if (tid < 64) {
        float s = 0.f;
#pragma unroll
        for (int t = 0; t < 16; ++t) s += Wsm[t * 64 + tid];
        g_partial[blk * 128 + 64 + tid] = s;
    }
}

// ---------------- finalize BN stats (deterministic) -------------------------
__global__ void finalize_kernel(const float* __restrict__ gamma, const float* __restrict__ beta) {
    int d = threadIdx.x;  // 64 threads
    float s = 0.f, s2 = 0.f;
    const int nblk = Bb * Nn / 64;
#pragma unroll 8
    for (int blk = 0; blk < nblk; ++blk) {
        s += g_partial[blk * 128 + d];
        s2 += g_partial[blk * 128 + 64 + d];
    }
    const float inv = 1.0f / (float)(Bb * Nn);
    float mean = s * inv;
    float var = s2 * inv - mean * mean;
    float sc = gamma[d] * rsqrtf(var + 1e-5f);
    g_scale[d] = sc;
    g_shift[d] = beta[d] - mean * sc;
}

// ---------------- apply BN in place on d_out --------------------------------
__global__ void bn_apply(float* __restrict__ out) {
    int i = blockIdx.x * 256 + threadIdx.x;  // float4 index; 8192/4=2048 per d-row
    float4 v = ((float4*)out)[i];
    int d = (i >> 11) & 63;
    float sc = g_scale[d], sh = g_shift[d];
    v.x = fmaf(v.x, sc, sh);
    v.y = fmaf(v.y, sc, sh);
    v.z = fmaf(v.z, sc, sh);
    v.w = fmaf(v.w, sc, sh);
    ((float4*)out)[i] = v;
}

// ---------------- launch ----------------------------------------------------
extern "C" void kernel_launch(void* const* d_in, const int* in_sizes, int n_in,
                              void* d_out, int out_size) {
    const float* x = (const float*)d_in[0];
    const float* pos = (const float*)d_in[1];
    const float* filt = (const float*)d_in[2];
    const float* gamma = (const float*)d_in[3];
    const float* beta = (const float*)d_in[4];
    float* out = (float*)d_out;

    prep_sq<<<dim3(Nn / 256, Bb), 256>>>(pos);
    prep_xT<<<dim3(Nn / 32, Cc / 32, Bb), dim3(32, 8)>>>(x);
    prep_wsum<<<(Cc * Dd) / 256, 256>>>(filt);
    knn_kernel<<<dim3(Nn / 256, Bb), 256>>>(pos);
    gconv_kernel<<<dim3(Nn / 64, Bb), 256>>>(filt, out);
    finalize_kernel<<<1, 64>>>(gamma, beta);
    bn_apply<<<(Bb * Dd * Nn / 4) / 256, 256>>>(out);
}

// round 3
// speedup vs baseline: 2.7132x; 2.7132x over previous
#include <cuda_runtime.h>

#define Bb 4
#define Cc 64
#define Nn 8192
#define Kk 16
#define Dd 64

// ---------------- scratch (static __device__, no allocations) ----------------
__device__ __align__(16) float g_xT[Bb * Nn * Cc];       // x transposed: (B, N, C)
__device__ float g_sq[Bb * Nn];                          // squared norms of pos
__device__ int   g_idx[Bb * Nn * Kk];                    // knn indices
__device__ __align__(16) float g_WsumNeg[Cc * Dd];       // -sum_k W[k,c,d]
__device__ float g_partial[(Bb * Nn / 64) * 2 * Dd];     // per-block BN partials (sum, sumsq)
__device__ float g_scale[Dd], g_shift[Dd];

// ---------------- prep: squared norms of pos --------------------------------
// Match XLA reduce lowering exactly: ((x*x + y*y) + z*z), no fma contraction.
__global__ void prep_sq(const float* __restrict__ pos) {
    int b = blockIdx.y;
    int n = blockIdx.x * 256 + threadIdx.x;
    const float* pb = pos + b * 3 * Nn;
    float x = pb[n], y = pb[Nn + n], z = pb[2 * Nn + n];
    float s = __fadd_rn(__fadd_rn(__fmul_rn(x, x), __fmul_rn(y, y)), __fmul_rn(z, z));
    g_sq[b * Nn + n] = s;
}

// ---------------- prep: transpose x (B,C,N) -> xT (B,N,C) -------------------
__global__ void prep_xT(const float* __restrict__ x) {
    __shared__ float t[32][33];
    int b = blockIdx.z;
    int n0 = blockIdx.x * 32, c0 = blockIdx.y * 32;
    int tx = threadIdx.x, ty = threadIdx.y;
#pragma unroll
    for (int i = 0; i < 4; ++i)
        t[ty + 8 * i][tx] = x[(size_t)b * Cc * Nn + (size_t)(c0 + ty + 8 * i) * Nn + n0 + tx];
    __syncthreads();
#pragma unroll
    for (int i = 0; i < 4; ++i)
        g_xT[(size_t)b * Nn * Cc + (size_t)(n0 + ty + 8 * i) * Cc + c0 + tx] = t[tx][ty + 8 * i];
}

// ---------------- prep: negated filter k-sum --------------------------------
__global__ void prep_wsum(const float* __restrict__ filt) {
    int i = blockIdx.x * 256 + threadIdx.x;  // 0..4095 = c*64+d
    float s = 0.f;
#pragma unroll
    for (int k = 0; k < Kk; ++k) s += filt[k * Cc * Dd + i];
    g_WsumNeg[i] = -s;
}

// ---------------- KNN --------------------------------------------------------
// Key: (sortable(dn) << 32) | ~idx  -> total order == top_k (value desc, idx asc).
// Keys are UNIQUE (idx unique), so order of insertion is irrelevant and
// replace-min-by-equality-scan is exact.
__device__ __forceinline__ unsigned long long knn_key(float dn, int j) {
    int bi = __float_as_int(dn);
    unsigned u = (unsigned)(bi ^ ((bi >> 31) | 0x80000000));
    return ((unsigned long long)u << 32) | (unsigned)(~j);
}
__device__ __forceinline__ unsigned long long um64(unsigned long long a, unsigned long long b) {
    return a < b ? a : b;
}

#define BUFCAP 12

__global__ void __launch_bounds__(128) knn_kernel(const float* __restrict__ pos) {
    __shared__ __align__(16) float4 tile[2048];
    __shared__ unsigned long long sbuf[BUFCAP][128];
    int b = blockIdx.y;
    int tid = threadIdx.x;
    int n = blockIdx.x * 128 + tid;
    const float* pb = pos + b * 3 * Nn;
    float qx = pb[n], qy = pb[Nn + n], qz = pb[2 * Nn + n];
    float qs = g_sq[b * Nn + n];

    // sentinel keys: decode to -inf, distinct, below any real key
    unsigned long long kl[16];
#pragma unroll
    for (int t = 0; t < 16; ++t) kl[t] = (0x007FFFFFull << 32) | (unsigned)t;
    unsigned long long kmin = kl[0];
    float vminf = __int_as_float(0xFF800000);  // -inf
    int cnt = 0;

    for (int t0 = 0; t0 < Nn; t0 += 2048) {
        __syncthreads();
        for (int i = tid; i < 2048; i += 128) {
            int j = t0 + i;
            tile[i] = make_float4(pb[j], pb[Nn + j], pb[2 * Nn + j], g_sq[b * Nn + j]);
        }
        __syncthreads();
        for (int jb = 0; jb < 2048; jb += 4) {
            float4 c0 = tile[jb + 0], c1 = tile[jb + 1], c2 = tile[jb + 2], c3 = tile[jb + 3];
            float d0 = __fadd_rn(__fmaf_rn(2.0f, __fmaf_rn(qz, c0.z, __fmaf_rn(qy, c0.y, __fmul_rn(qx, c0.x))), -qs), -c0.w);
            float d1 = __fadd_rn(__fmaf_rn(2.0f, __fmaf_rn(qz, c1.z, __fmaf_rn(qy, c1.y, __fmul_rn(qx, c1.x))), -qs), -c1.w);
            float d2 = __fadd_rn(__fmaf_rn(2.0f, __fmaf_rn(qz, c2.z, __fmaf_rn(qy, c2.y, __fmul_rn(qx, c2.x))), -qs), -c2.w);
            float d3 = __fadd_rn(__fmaf_rn(2.0f, __fmaf_rn(qz, c3.z, __fmaf_rn(qy, c3.y, __fmul_rn(qx, c3.x))), -qs), -c3.w);
            bool p0 = d0 >= vminf, p1 = d1 >= vminf, p2 = d2 >= vminf, p3 = d3 >= vminf;
            if (p0 | p1 | p2 | p3) {
                int jg = t0 + jb;
                if (p0) { sbuf[cnt][tid] = knn_key(d0, jg + 0); cnt++; }
                if (p1) { sbuf[cnt][tid] = knn_key(d1, jg + 1); cnt++; }
                if (p2) { sbuf[cnt][tid] = knn_key(d2, jg + 2); cnt++; }
                if (p3) { sbuf[cnt][tid] = knn_key(d3, jg + 3); cnt++; }
            }
            if (__any_sync(0xFFFFFFFFu, cnt > 8)) {
                int mx = (int)__reduce_max_sync(0xFFFFFFFFu, (unsigned)cnt);
                for (int m = 0; m < mx; ++m) {
                    unsigned long long kc = sbuf[m][tid];
                    bool take = (m < cnt) && (kc > kmin);
                    unsigned long long km = kmin;
#pragma unroll
                    for (int t = 0; t < 16; ++t) kl[t] = (take && kl[t] == km) ? kc : kl[t];
                    unsigned long long a0 = um64(kl[0], kl[1]), a1 = um64(kl[2], kl[3]);
                    unsigned long long a2 = um64(kl[4], kl[5]), a3 = um64(kl[6], kl[7]);
                    unsigned long long a4 = um64(kl[8], kl[9]), a5 = um64(kl[10], kl[11]);
                    unsigned long long a6 = um64(kl[12], kl[13]), a7 = um64(kl[14], kl[15]);
                    a0 = um64(a0, a1); a2 = um64(a2, a3); a4 = um64(a4, a5); a6 = um64(a6, a7);
                    kmin = um64(um64(a0, a2), um64(a4, a6));
                }
                cnt = 0;
                unsigned u = (unsigned)(kmin >> 32);
                unsigned tb = (u & 0x80000000u) ? (u ^ 0x80000000u) : ~u;
                vminf = __int_as_float((int)tb);
            }
        }
    }
    // final compaction
    {
        int mx = (int)__reduce_max_sync(0xFFFFFFFFu, (unsigned)cnt);
        for (int m = 0; m < mx; ++m) {
            unsigned long long kc = sbuf[m][tid];
            bool take = (m < cnt) && (kc > kmin);
            unsigned long long km = kmin;
#pragma unroll
            for (int t = 0; t < 16; ++t) kl[t] = (take && kl[t] == km) ? kc : kl[t];
            unsigned long long a0 = um64(kl[0], kl[1]), a1 = um64(kl[2], kl[3]);
            unsigned long long a2 = um64(kl[4], kl[5]), a3 = um64(kl[6], kl[7]);
            unsigned long long a4 = um64(kl[8], kl[9]), a5 = um64(kl[10], kl[11]);
            unsigned long long a6 = um64(kl[12], kl[13]), a7 = um64(kl[14], kl[15]);
            a0 = um64(a0, a1); a2 = um64(a2, a3); a4 = um64(a4, a5); a6 = um64(a6, a7);
            kmin = um64(um64(a0, a2), um64(a4, a6));
        }
    }
    // sort 16 keys descending (odd-even transposition, static indexing)
#pragma unroll
    for (int pass = 0; pass < 16; ++pass) {
#pragma unroll
        for (int t = (pass & 1); t < 15; t += 2) {
            unsigned long long lo = um64(kl[t], kl[t + 1]);
            unsigned long long hi = (kl[t] < kl[t + 1]) ? kl[t + 1] : kl[t];
            kl[t] = hi; kl[t + 1] = lo;
        }
    }
#pragma unroll
    for (int t = 0; t < 16; ++t)
        g_idx[((size_t)b * Nn + n) * Kk + t] = (int)(~(unsigned)kl[t]);
}

// ---------------- fused gather + spectral GEMM + BN partials ----------------
__global__ void gconv_kernel(const float* __restrict__ filt, float* __restrict__ out) {
    __shared__ __align__(16) float Esm[64 * 64];  // [c][p]
    __shared__ __align__(16) float Wsm[64 * 64];  // [c][d]
    int b = blockIdx.y;
    int n0 = blockIdx.x * 64;
    int tid = threadIdx.x;
    int tx = tid & 15, ty = tid >> 4;         // d-quad, p-quad
    int p = tid & 63, cg = tid >> 6;          // staging roles

    float acc[4][4];
#pragma unroll
    for (int i = 0; i < 4; ++i)
#pragma unroll
        for (int j = 0; j < 4; ++j) acc[i][j] = 0.f;

    const float* xTb = g_xT + (size_t)b * Nn * Cc;

    for (int kk = 0; kk <= Kk; ++kk) {
        const float* Wsrc = (kk < Kk) ? (filt + kk * Cc * Dd) : g_WsumNeg;
#pragma unroll
        for (int i = 0; i < 4; ++i)
            ((float4*)Wsm)[tid + 256 * i] = ((const float4*)Wsrc)[tid + 256 * i];
        int m = (kk < Kk) ? g_idx[((size_t)b * Nn + n0 + p) * Kk + kk] : (n0 + p);
        const float* row = xTb + (size_t)m * Cc + cg * 16;
#pragma unroll
        for (int i = 0; i < 4; ++i) {
            float4 vv = ((const float4*)row)[i];
            int c = cg * 16 + i * 4;
            Esm[(c + 0) * 64 + p] = vv.x;
            Esm[(c + 1) * 64 + p] = vv.y;
            Esm[(c + 2) * 64 + p] = vv.z;
            Esm[(c + 3) * 64 + p] = vv.w;
        }
        __syncthreads();
#pragma unroll 8
        for (int c = 0; c < 64; ++c) {
            float4 e = *(const float4*)&Esm[c * 64 + ty * 4];
            float4 w = *(const float4*)&Wsm[c * 64 + tx * 4];
            acc[0][0] = fmaf(e.x, w.x, acc[0][0]);
            acc[0][1] = fmaf(e.x, w.y, acc[0][1]);
            acc[0][2] = fmaf(e.x, w.z, acc[0][2]);
            acc[0][3] = fmaf(e.x, w.w, acc[0][3]);
            acc[1][0] = fmaf(e.y, w.x, acc[1][0]);
            acc[1][1] = fmaf(e.y, w.y, acc[1][1]);
            acc[1][2] = fmaf(e.y, w.z, acc[1][2]);
            acc[1][3] = fmaf(e.y, w.w, acc[1][3]);
            acc[2][0] = fmaf(e.z, w.x, acc[2][0]);
            acc[2][1] = fmaf(e.z, w.y, acc[2][1]);
            acc[2][2] = fmaf(e.z, w.z, acc[2][2]);
            acc[2][3] = fmaf(e.z, w.w, acc[2][3]);
            acc[3][0] = fmaf(e.w, w.x, acc[3][0]);
            acc[3][1] = fmaf(e.w, w.y, acc[3][1]);
            acc[3][2] = fmaf(e.w, w.z, acc[3][2]);
            acc[3][3] = fmaf(e.w, w.w, acc[3][3]);
        }
        __syncthreads();
    }

    float psum[4], psq[4];
#pragma unroll
    for (int j = 0; j < 4; ++j) {
        psum[j] = acc[0][j] + acc[1][j] + acc[2][j] + acc[3][j];
        psq[j] = acc[0][j] * acc[0][j] + acc[1][j] * acc[1][j] +
                 acc[2][j] * acc[2][j] + acc[3][j] * acc[3][j];
    }
#pragma unroll
    for (int i = 0; i < 4; ++i)
#pragma unroll
        for (int j = 0; j < 4; ++j)
            Esm[(tx * 4 + j) * 64 + (ty * 4 + i)] = acc[i][j];
#pragma unroll
    for (int j = 0; j < 4; ++j) Wsm[ty * 64 + tx * 4 + j] = psum[j];
    __syncthreads();

    {
        int d = tid >> 2, seg = tid & 3;
        float4* orow = (float4*)(out + (size_t)b * Dd * Nn + (size_t)d * Nn + n0);
        const float4* trow = (const float4*)&Esm[d * 64];
#pragma unroll
        for (int q = 0; q < 4; ++q) orow[seg * 4 + q] = trow[seg * 4 + q];
    }
    int blk = b * gridDim.x + blockIdx.x;
    if (tid < 64) {
        float s = 0.f;
#pragma unroll
        for (int t = 0; t < 16; ++t) s += Wsm[t * 64 + tid];
        g_partial[blk * 128 + tid] = s;
    }
    __syncthreads();
#pragma unroll
    for (int j = 0; j < 4; ++j) Wsm[ty * 64 + tx * 4 + j] = psq[j];
    __syncthreads();
    if (tid < 64) {
        float s = 0.f;
#pragma unroll
        for (int t = 0; t < 16; ++t) s += Wsm[t * 64 + tid];
        g_partial[blk * 128 + 64 + tid] = s;
    }
}

// ---------------- finalize BN stats (deterministic) -------------------------
__global__ void finalize_kernel(const float* __restrict__ gamma, const float* __restrict__ beta) {
    int d = threadIdx.x;  // 64 threads
    float s = 0.f, s2 = 0.f;
    const int nblk = Bb * Nn / 64;
#pragma unroll 8
    for (int blk = 0; blk < nblk; ++blk) {
        s += g_partial[blk * 128 + d];
        s2 += g_partial[blk * 128 + 64 + d];
    }
    const float inv = 1.0f / (float)(Bb * Nn);
    float mean = s * inv;
    float var = s2 * inv - mean * mean;
    float sc = gamma[d] * rsqrtf(var + 1e-5f);
    g_scale[d] = sc;
    g_shift[d] = beta[d] - mean * sc;
}

// ---------------- apply BN in place on d_out --------------------------------
__global__ void bn_apply(float* __restrict__ out) {
    int i = blockIdx.x * 256 + threadIdx.x;
    float4 v = ((float4*)out)[i];
    int d = (i >> 11) & 63;
    float sc = g_scale[d], sh = g_shift[d];
    v.x = fmaf(v.x, sc, sh);
    v.y = fmaf(v.y, sc, sh);
    v.z = fmaf(v.z, sc, sh);
    v.w = fmaf(v.w, sc, sh);
    ((float4*)out)[i] = v;
}

// ---------------- launch ----------------------------------------------------
extern "C" void kernel_launch(void* const* d_in, const int* in_sizes, int n_in,
                              void* d_out, int out_size) {
    const float* x = (const float*)d_in[0];
    const float* pos = (const float*)d_in[1];
    const float* filt = (const float*)d_in[2];
    const float* gamma = (const float*)d_in[3];
    const float* beta = (const float*)d_in[4];
    float* out = (float*)d_out;

    prep_sq<<<dim3(Nn / 256, Bb), 256>>>(pos);
    prep_xT<<<dim3(Nn / 32, Cc / 32, Bb), dim3(32, 8)>>>(x);
    prep_wsum<<<(Cc * Dd) / 256, 256>>>(filt);
    knn_kernel<<<dim3(Nn / 128, Bb), 128>>>(pos);
    gconv_kernel<<<dim3(Nn / 64, Bb), 256>>>(filt, out);
    finalize_kernel<<<1, 64>>>(gamma, beta);
    bn_apply<<<(Bb * Dd * Nn / 4) / 256, 256>>>(out);
}